// round 1
// baseline (speedup 1.0000x reference)
#include <cuda_runtime.h>
#include <cfloat>

#define BB 2048
#define TT 32
#define VV 1024
#define DD 256

// scratch for c2[t][v] = sum_d codebook[t,v,d]^2   (128 KB, static device array)
__device__ float g_c2[TT * VV];

// ---------------------------------------------------------------------------
// Kernel 1: c2[t][v] — one warp per (t,v) row of 256 floats
// ---------------------------------------------------------------------------
__global__ __launch_bounds__(256) void c2_kernel(const float* __restrict__ cb) {
    int row  = blockIdx.x * 8 + (threadIdx.x >> 5);   // 0 .. 32767
    int lane = threadIdx.x & 31;
    const float4* p = reinterpret_cast<const float4*>(cb) + (size_t)row * (DD / 4);
    float s = 0.f;
#pragma unroll
    for (int q = 0; q < 2; q++) {
        float4 v = p[lane + 32 * q];
        s = fmaf(v.x, v.x, s);
        s = fmaf(v.y, v.y, s);
        s = fmaf(v.z, v.z, s);
        s = fmaf(v.w, v.w, s);
    }
#pragma unroll
    for (int o = 16; o > 0; o >>= 1) s += __shfl_down_sync(0xffffffffu, s, o);
    if (lane == 0) g_c2[row] = s;
}

// ---------------------------------------------------------------------------
// Kernel 2: fused GEMM (x . c^T) + argmin over V + gather epilogue.
// Grid: (16 b-tiles, 32 t). Block: 256 threads as 16x16, 8x8 microtile.
// Tile: 128 rows(b) x 128 cols(v), k-tile 16, loop 8 v-chunks with running min.
// score = c2[v] - 2*dot(x,c)   (x2 is constant per row -> same argmin)
// ---------------------------------------------------------------------------
__global__ __launch_bounds__(256) void vsq_kernel(const float* __restrict__ x,
                                                  const float* __restrict__ cb,
                                                  float* __restrict__ out) {
    const int btile = blockIdx.x;   // 0..15
    const int t     = blockIdx.y;   // 0..31
    const int tid   = threadIdx.x;
    const int ty    = tid >> 4;     // 0..15
    const int tx    = tid & 15;     // 0..15

    __shared__ float Xs[16 * 128];  // [k][row]
    __shared__ float Cs[16 * 128];  // [k][col]
    __shared__ float Sv[128 * 16];
    __shared__ int   Si[128 * 16];
    __shared__ int   rowIdx[128];

    float bestv[8];
    int   besti[8];
#pragma unroll
    for (int i = 0; i < 8; i++) { bestv[i] = FLT_MAX; besti[i] = 0; }

    const float* xbase  = x  + (((size_t)btile * 128) * TT + t) * DD;
    const float* cbbase = cb + ((size_t)t * VV) * DD;

    for (int vc = 0; vc < 8; vc++) {
        float acc[8][8];
#pragma unroll
        for (int i = 0; i < 8; i++)
#pragma unroll
            for (int j = 0; j < 8; j++) acc[i][j] = 0.f;

        for (int k0 = 0; k0 < DD; k0 += 16) {
            __syncthreads();
            // load 128x16 X tile and 128x16 C tile (2 float4 each per thread)
#pragma unroll
            for (int l = 0; l < 2; l++) {
                int f   = tid + l * 256;      // 0..511
                int row = f >> 2;             // 0..127
                int kk  = (f & 3) << 2;       // 0,4,8,12
                float4 vx = *reinterpret_cast<const float4*>(
                    xbase + (size_t)row * (TT * DD) + k0 + kk);
                Xs[(kk + 0) * 128 + row] = vx.x;
                Xs[(kk + 1) * 128 + row] = vx.y;
                Xs[(kk + 2) * 128 + row] = vx.z;
                Xs[(kk + 3) * 128 + row] = vx.w;
                float4 vcld = *reinterpret_cast<const float4*>(
                    cbbase + ((size_t)(vc * 128 + row)) * DD + k0 + kk);
                Cs[(kk + 0) * 128 + row] = vcld.x;
                Cs[(kk + 1) * 128 + row] = vcld.y;
                Cs[(kk + 2) * 128 + row] = vcld.z;
                Cs[(kk + 3) * 128 + row] = vcld.w;
            }
            __syncthreads();
#pragma unroll
            for (int k = 0; k < 16; k++) {
                float xr[8], cr[8];
#pragma unroll
                for (int i = 0; i < 8; i++) xr[i] = Xs[k * 128 + ty * 8 + i];
#pragma unroll
                for (int j = 0; j < 8; j++) cr[j] = Cs[k * 128 + tx * 8 + j];
#pragma unroll
                for (int i = 0; i < 8; i++)
#pragma unroll
                    for (int j = 0; j < 8; j++)
                        acc[i][j] = fmaf(xr[i], cr[j], acc[i][j]);
            }
        }
        // fold c2 and update running argmin (ascending idx order per thread)
#pragma unroll
        for (int j = 0; j < 8; j++) {
            int v    = vc * 128 + tx * 8 + j;
            float cc = g_c2[t * VV + v];
#pragma unroll
            for (int i = 0; i < 8; i++) {
                float s = fmaf(-2.f, acc[i][j], cc);
                if (s < bestv[i]) { bestv[i] = s; besti[i] = v; }
            }
        }
    }

    // cross-thread reduction: 16 candidates per row
    __syncthreads();
#pragma unroll
    for (int i = 0; i < 8; i++) {
        Sv[(ty * 8 + i) * 16 + tx] = bestv[i];
        Si[(ty * 8 + i) * 16 + tx] = besti[i];
    }
    __syncthreads();
    if (tid < 128) {
        float bv = Sv[tid * 16];
        int   bi = Si[tid * 16];
#pragma unroll
        for (int u = 1; u < 16; u++) {
            float v2 = Sv[tid * 16 + u];
            int   i2 = Si[tid * 16 + u];
            if (v2 < bv || (v2 == bv && i2 < bi)) { bv = v2; bi = i2; }
        }
        rowIdx[tid] = bi;
        int b = btile * 128 + tid;
        // idxes output region: after embed (B*T*D floats), layout (B,T)
        out[(size_t)BB * TT * DD + (size_t)b * TT + t] = (float)bi;
    }
    __syncthreads();

    // gather epilogue: embed[b,t,:] = codebook[t, idx, :]
    const float4* cb4  = reinterpret_cast<const float4*>(cb);
    float4*       out4 = reinterpret_cast<float4*>(out);
    int rsub = tid >> 6;   // 0..3
    int d4   = tid & 63;   // 0..63
#pragma unroll 4
    for (int r0 = 0; r0 < 128; r0 += 4) {
        int r   = r0 + rsub;
        int b   = btile * 128 + r;
        int idx = rowIdx[r];
        out4[((size_t)b * TT + t) * (DD / 4) + d4] =
            cb4[((size_t)t * VV + idx) * (DD / 4) + d4];
    }
}

// ---------------------------------------------------------------------------
extern "C" void kernel_launch(void* const* d_in, const int* in_sizes, int n_in,
                              void* d_out, int out_size) {
    const float* x  = (const float*)d_in[0];   // (B, T, D) f32
    const float* cb = (const float*)d_in[1];   // (T, V, D) f32
    float* out = (float*)d_out;                // [B*T*D embed | B*T idx-as-float]

    c2_kernel<<<(TT * VV) / 8, 256>>>(cb);
    dim3 grid(BB / 128, TT);
    vsq_kernel<<<grid, 256>>>(x, cb, out);
}

// round 3
// speedup vs baseline: 1.2407x; 1.2407x over previous
#include <cuda_runtime.h>
#include <cfloat>
#include <cstdint>

#define BB 2048
#define TT 32
#define VV 1024
#define DD 256

__device__ float g_c2[TT * VV];

// ---------------- helpers ----------------------------------------------------
__device__ __forceinline__ float tf32_rna(float x) {
    uint32_t u;
    asm("cvt.rna.tf32.f32 %0, %1;" : "=r"(u) : "f"(x));
    return __uint_as_float(u);
}

__device__ __forceinline__ void mma_tf32(float* c, const uint32_t* a, const uint32_t* b) {
    asm volatile(
        "mma.sync.aligned.m16n8k8.row.col.f32.tf32.tf32.f32 "
        "{%0,%1,%2,%3}, {%4,%5,%6,%7}, {%8,%9}, {%0,%1,%2,%3};"
        : "+f"(c[0]), "+f"(c[1]), "+f"(c[2]), "+f"(c[3])
        : "r"(a[0]), "r"(a[1]), "r"(a[2]), "r"(a[3]), "r"(b[0]), "r"(b[1]));
}

// ---------------- kernel 1: c2[t][v] -----------------------------------------
__global__ __launch_bounds__(256) void c2_kernel(const float* __restrict__ cb) {
    int row  = blockIdx.x * 8 + (threadIdx.x >> 5);
    int lane = threadIdx.x & 31;
    const float4* p = reinterpret_cast<const float4*>(cb) + (size_t)row * (DD / 4);
    float s = 0.f;
#pragma unroll
    for (int q = 0; q < 2; q++) {
        float4 v = p[lane + 32 * q];
        s = fmaf(v.x, v.x, s); s = fmaf(v.y, v.y, s);
        s = fmaf(v.z, v.z, s); s = fmaf(v.w, v.w, s);
    }
#pragma unroll
    for (int o = 16; o > 0; o >>= 1) s += __shfl_down_sync(0xffffffffu, s, o);
    if (lane == 0) g_c2[row] = s;
}

// ---------------- main kernel ------------------------------------------------
// Grid (16, 32). Block 256 = 8 warps (2m x 4n). Block tile 128(b) x 128(v).
// K slabs of 16, tf32 split on the fly into smem (hi & lo), 3-term mma.
#define KC 16
#define PITCH 18                      // 16 + 2 pad: conflict-free frag loads
#define HALF_SZ (128 * PITCH)         // floats per hi/lo plane
#define OP_SZ   (2 * HALF_SZ)         // one operand (hi + lo)

__global__ __launch_bounds__(256, 2)
void vsq_mma_kernel(const float* __restrict__ x, const float* __restrict__ cb,
                    float* __restrict__ out) {
    extern __shared__ float sm[];
    float* As  = sm;                  // [2][128][PITCH]
    float* Bs  = sm + OP_SZ;          // [2][128][PITCH]
    float* c2s = Bs + OP_SZ;          // [1024]
    float* Sv  = c2s + VV;            // [128][16]
    int*   Si  = (int*)(Sv + 128 * 16);
    int*   ridx = Si + 128 * 16;      // [128]

    const int tid  = threadIdx.x;
    const int btile = blockIdx.x, t = blockIdx.y;
    const int wid = tid >> 5, lane = tid & 31;
    const int grp = lane >> 2, tig = lane & 3;
    const int wm = wid >> 2, wn = wid & 3;

    for (int i = tid; i < VV; i += 256) c2s[i] = g_c2[t * VV + i];

    float bestv[8];
    int   besti[8];
#pragma unroll
    for (int i = 0; i < 8; i++) { bestv[i] = FLT_MAX; besti[i] = 0; }

    // load assignment: thread covers (row = tid>>2, row+64) x (k4 = tid&3)
    const int lrow = tid >> 2, lk4 = tid & 3;
    const float* Ar0 = x + ((size_t)(btile * 128 + lrow) * TT + t) * DD + lk4 * 4;
    const float* Ar1 = Ar0 + (size_t)64 * TT * DD;
    const float* cbt = cb + (size_t)t * VV * DD;

    for (int nch = 0; nch < 8; nch++) {
        const float* Br0 = cbt + (size_t)(nch * 128 + lrow) * DD + lk4 * 4;
        const float* Br1 = Br0 + (size_t)64 * DD;

        float acc[4][4][4];
#pragma unroll
        for (int a = 0; a < 4; a++)
#pragma unroll
            for (int b = 0; b < 4; b++)
#pragma unroll
                for (int c = 0; c < 4; c++) acc[a][b][c] = 0.f;

        float4 ra0 = *reinterpret_cast<const float4*>(Ar0);
        float4 ra1 = *reinterpret_cast<const float4*>(Ar1);
        float4 rb0 = *reinterpret_cast<const float4*>(Br0);
        float4 rb1 = *reinterpret_cast<const float4*>(Br1);

        for (int ks = 0; ks < DD / KC; ks++) {
            __syncthreads();
            // convert + store current slab
            {
                float va[8] = { ra0.x, ra0.y, ra0.z, ra0.w, ra1.x, ra1.y, ra1.z, ra1.w };
                float vb[8] = { rb0.x, rb0.y, rb0.z, rb0.w, rb1.x, rb1.y, rb1.z, rb1.w };
#pragma unroll
                for (int h = 0; h < 2; h++) {
                    int row = lrow + h * 64;
#pragma unroll
                    for (int j = 0; j < 4; j++) {
                        float v  = va[h * 4 + j];
                        float hi = tf32_rna(v);
                        float lo = tf32_rna(v - hi);
                        As[row * PITCH + lk4 * 4 + j]           = hi;
                        As[HALF_SZ + row * PITCH + lk4 * 4 + j] = lo;
                        float w  = vb[h * 4 + j];
                        float wh = tf32_rna(w);
                        float wl = tf32_rna(w - wh);
                        Bs[row * PITCH + lk4 * 4 + j]           = wh;
                        Bs[HALF_SZ + row * PITCH + lk4 * 4 + j] = wl;
                    }
                }
            }
            __syncthreads();
            // prefetch next slab
            if (ks < DD / KC - 1) {
                int k0 = (ks + 1) * KC;
                ra0 = *reinterpret_cast<const float4*>(Ar0 + k0);
                ra1 = *reinterpret_cast<const float4*>(Ar1 + k0);
                rb0 = *reinterpret_cast<const float4*>(Br0 + k0);
                rb1 = *reinterpret_cast<const float4*>(Br1 + k0);
            }
            // mma over the slab: 2 ksteps of 8
#pragma unroll
            for (int kp = 0; kp < 2; kp++) {
                uint32_t ah[4][4], al[4][4];
#pragma unroll
                for (int mt = 0; mt < 4; mt++) {
                    int base = (wm * 64 + mt * 16 + grp) * PITCH + kp * 8 + tig;
                    ah[mt][0] = __float_as_uint(As[base]);
                    ah[mt][1] = __float_as_uint(As[base + 8 * PITCH]);
                    ah[mt][2] = __float_as_uint(As[base + 4]);
                    ah[mt][3] = __float_as_uint(As[base + 8 * PITCH + 4]);
                    al[mt][0] = __float_as_uint(As[HALF_SZ + base]);
                    al[mt][1] = __float_as_uint(As[HALF_SZ + base + 8 * PITCH]);
                    al[mt][2] = __float_as_uint(As[HALF_SZ + base + 4]);
                    al[mt][3] = __float_as_uint(As[HALF_SZ + base + 8 * PITCH + 4]);
                }
#pragma unroll
                for (int nt = 0; nt < 4; nt++) {
                    int bb = (wn * 32 + nt * 8 + grp) * PITCH + kp * 8 + tig;
                    uint32_t bh[2], bl[2];
                    bh[0] = __float_as_uint(Bs[bb]);
                    bh[1] = __float_as_uint(Bs[bb + 4]);
                    bl[0] = __float_as_uint(Bs[HALF_SZ + bb]);
                    bl[1] = __float_as_uint(Bs[HALF_SZ + bb + 4]);
#pragma unroll
                    for (int mt = 0; mt < 4; mt++) {
                        mma_tf32(acc[mt][nt], ah[mt], bh);   // hi*hi
                        mma_tf32(acc[mt][nt], ah[mt], bl);   // hi*lo
                        mma_tf32(acc[mt][nt], al[mt], bh);   // lo*hi
                    }
                }
            }
        }
        // fold c2, update running argmin (v ascending within thread)
#pragma unroll
        for (int nt = 0; nt < 4; nt++) {
            int vbase = nch * 128 + wn * 32 + nt * 8 + tig * 2;
            float c0 = c2s[vbase], c1 = c2s[vbase + 1];
#pragma unroll
            for (int mt = 0; mt < 4; mt++) {
                float s0 = fmaf(-2.f, acc[mt][nt][0], c0);
                float s1 = fmaf(-2.f, acc[mt][nt][1], c1);
                float s2 = fmaf(-2.f, acc[mt][nt][2], c0);
                float s3 = fmaf(-2.f, acc[mt][nt][3], c1);
                int sl0 = mt * 2, sl1 = mt * 2 + 1;
                if (s0 < bestv[sl0]) { bestv[sl0] = s0; besti[sl0] = vbase; }
                if (s1 < bestv[sl0]) { bestv[sl0] = s1; besti[sl0] = vbase + 1; }
                if (s2 < bestv[sl1]) { bestv[sl1] = s2; besti[sl1] = vbase; }
                if (s3 < bestv[sl1]) { bestv[sl1] = s3; besti[sl1] = vbase + 1; }
            }
        }
    }

    // cross-thread reduce: 16 candidates per row
    __syncthreads();
#pragma unroll
    for (int mt = 0; mt < 4; mt++) {
#pragma unroll
        for (int h = 0; h < 2; h++) {
            int r = wm * 64 + mt * 16 + grp + h * 8;
            Sv[r * 16 + wn * 4 + tig] = bestv[mt * 2 + h];
            Si[r * 16 + wn * 4 + tig] = besti[mt * 2 + h];
        }
    }
    __syncthreads();
    if (tid < 128) {
        float bv = Sv[tid * 16];
        int   bi = Si[tid * 16];
#pragma unroll
        for (int u = 1; u < 16; u++) {
            float v2 = Sv[tid * 16 + u];
            int   i2 = Si[tid * 16 + u];
            if (v2 < bv || (v2 == bv && i2 < bi)) { bv = v2; bi = i2; }
        }
        ridx[tid] = bi;
        int b = btile * 128 + tid;
        out[(size_t)BB * TT * DD + (size_t)b * TT + t] = (float)bi;
    }
    __syncthreads();

    // gather epilogue
    const float4* cb4  = reinterpret_cast<const float4*>(cb);
    float4*       out4 = reinterpret_cast<float4*>(out);
    int rsub = tid >> 6, d4 = tid & 63;
#pragma unroll 4
    for (int r0 = 0; r0 < 128; r0 += 4) {
        int r   = r0 + rsub;
        int b   = btile * 128 + r;
        int idx = ridx[r];
        out4[((size_t)b * TT + t) * (DD / 4) + d4] =
            cb4[((size_t)t * VV + idx) * (DD / 4) + d4];
    }
}

// ---------------------------------------------------------------------------
#define DYN_SMEM ((2 * OP_SZ + VV + 128 * 16 * 2 + 128) * 4)

extern "C" void kernel_launch(void* const* d_in, const int* in_sizes, int n_in,
                              void* d_out, int out_size) {
    const float* x  = (const float*)d_in[0];   // (B, T, D) f32
    const float* cb = (const float*)d_in[1];   // (T, V, D) f32
    float* out = (float*)d_out;

    cudaFuncSetAttribute(vsq_mma_kernel, cudaFuncAttributeMaxDynamicSharedMemorySize, DYN_SMEM);
    c2_kernel<<<(TT * VV) / 8, 256>>>(cb);
    vsq_mma_kernel<<<dim3(BB / 128, TT), 256, DYN_SMEM>>>(x, cb, out);
}

// round 4
// speedup vs baseline: 2.7511x; 2.2174x over previous
#include <cuda_runtime.h>
#include <cuda_fp16.h>
#include <cfloat>
#include <cstdint>

#define BB 2048
#define TT 32
#define VV 1024
#define DD 256

__device__ float g_c2[TT * VV];

// ---------------- helpers ----------------------------------------------------
__device__ __forceinline__ void mma_f16(float* c, uint32_t a0, uint32_t a1,
                                        uint32_t a2, uint32_t a3,
                                        uint32_t b0, uint32_t b1) {
    asm volatile(
        "mma.sync.aligned.m16n8k16.row.col.f32.f16.f16.f32 "
        "{%0,%1,%2,%3}, {%4,%5,%6,%7}, {%8,%9}, {%0,%1,%2,%3};"
        : "+f"(c[0]), "+f"(c[1]), "+f"(c[2]), "+f"(c[3])
        : "r"(a0), "r"(a1), "r"(a2), "r"(a3), "r"(b0), "r"(b1));
}

// ---------------- kernel 1: c2[t][v] -----------------------------------------
__global__ __launch_bounds__(256) void c2_kernel(const float* __restrict__ cb) {
    int row  = blockIdx.x * 8 + (threadIdx.x >> 5);
    int lane = threadIdx.x & 31;
    const float4* p = reinterpret_cast<const float4*>(cb) + (size_t)row * (DD / 4);
    float s = 0.f;
#pragma unroll
    for (int q = 0; q < 2; q++) {
        float4 v = p[lane + 32 * q];
        s = fmaf(v.x, v.x, s); s = fmaf(v.y, v.y, s);
        s = fmaf(v.z, v.z, s); s = fmaf(v.w, v.w, s);
    }
#pragma unroll
    for (int o = 16; o > 0; o >>= 1) s += __shfl_down_sync(0xffffffffu, s, o);
    if (lane == 0) g_c2[row] = s;
}

// ---------------- main kernel ------------------------------------------------
// Grid (16, 32). Block 256 = 8 warps (2m x 4n). Block tile 128(b) x 128(v).
// K slabs of 16. fp16 hi/lo split on the fly, stored FRAGMENT-MAJOR in smem:
// one LDS.128 per fragment. 3-term mma (hi*hi + hi*lo + lo*hi), f32 accum.
//
// A plane layout: 8 tiles (16 rows each) x 32 lanes x 4 regs(u32).
//   element (r,k): tile=r>>4, lane=swz((r&7)*4 + ((k&7)>>1)), reg=((r>>3)&1)+2*(k>>3)
// B plane layout: 8 pairs (16 n each) x 32 lanes x 4 regs.
//   element (n,k): q=n>>4, lane=swz((n&7)*4 + ((k&7)>>1)), reg=2*((n>>3)&1)+(k>>3)
// swz(l) = l ^ ((l>>3)&3)  (conflict-free stores AND loads)

__global__ __launch_bounds__(256, 2)
void vsq_mma_kernel(const float* __restrict__ x, const float* __restrict__ cb,
                    float* __restrict__ out) {
    extern __shared__ char smraw[];
    half2* Ahi = reinterpret_cast<half2*>(smraw);          // 1024 half2 (4KB)
    half2* Alo = Ahi + 1024;
    half2* Bhi = Alo + 1024;
    half2* Blo = Bhi + 1024;
    float* c2s = reinterpret_cast<float*>(Blo + 1024);     // 4KB
    float* Sv  = c2s + VV;                                 // 8KB
    int*   Si  = reinterpret_cast<int*>(Sv + 128 * 16);    // 8KB
    int*   ridx = Si + 128 * 16;                           // 512B

    const int tid = threadIdx.x;
    const int btile = blockIdx.x, t = blockIdx.y;
    const int wid = tid >> 5, lane = tid & 31;
    const int grp = lane >> 2, tig = lane & 3;
    const int wm = wid >> 2, wn = wid & 3;
    const int swl = lane ^ ((lane >> 3) & 3);

    for (int i = tid; i < VV; i += 256) c2s[i] = g_c2[t * VV + i];

    float bestv[8];
    int   besti[8];
#pragma unroll
    for (int i = 0; i < 8; i++) { bestv[i] = FLT_MAX; besti[i] = 0; }

    // loader assignment: rows (tid>>2, +64), k4 = tid&3 (4 consecutive k)
    const int lrow = tid >> 2, lk4 = tid & 3;
    const float* Ar0 = x + ((size_t)(btile * 128 + lrow) * TT + t) * DD + lk4 * 4;
    const float* Ar1 = Ar0 + (size_t)64 * TT * DD;
    const float* cbt = cb + (size_t)t * VV * DD;

    // precomputed store indices (half2 units) for the 2 k-pairs of this thread
    int aidx[2][2], bidx[2][2];      // [h(row half)][jp(k pair)]
#pragma unroll
    for (int h = 0; h < 2; h++) {
        int row = lrow + h * 64;
        int r7 = row & 7, rtop = (row >> 3) & 1;
        int tileA = row >> 4;
        int qB = row >> 4, subB = (row >> 3) & 1;
#pragma unroll
        for (int jp = 0; jp < 2; jp++) {
            int k0 = lk4 * 4 + jp * 2;
            int lk = r7 * 4 + ((k0 & 7) >> 1);
            int sl = lk ^ ((lk >> 3) & 3);
            aidx[h][jp] = tileA * 128 + sl * 4 + (rtop + 2 * (k0 >> 3));
            bidx[h][jp] = qB * 128 + sl * 4 + (2 * subB + (k0 >> 3));
        }
    }

    for (int nch = 0; nch < 8; nch++) {
        const float* Br0 = cbt + (size_t)(nch * 128 + lrow) * DD + lk4 * 4;
        const float* Br1 = Br0 + (size_t)64 * DD;

        float acc[4][4][4];
#pragma unroll
        for (int a = 0; a < 4; a++)
#pragma unroll
            for (int b = 0; b < 4; b++)
#pragma unroll
                for (int c = 0; c < 4; c++) acc[a][b][c] = 0.f;

        float4 ra0 = *reinterpret_cast<const float4*>(Ar0);
        float4 ra1 = *reinterpret_cast<const float4*>(Ar1);
        float4 rb0 = *reinterpret_cast<const float4*>(Br0);
        float4 rb1 = *reinterpret_cast<const float4*>(Br1);

        for (int ks = 0; ks < DD / 16; ks++) {
            __syncthreads();
            {
                float va[2][4] = {{ra0.x, ra0.y, ra0.z, ra0.w}, {ra1.x, ra1.y, ra1.z, ra1.w}};
                float vb[2][4] = {{rb0.x, rb0.y, rb0.z, rb0.w}, {rb1.x, rb1.y, rb1.z, rb1.w}};
#pragma unroll
                for (int h = 0; h < 2; h++) {
#pragma unroll
                    for (int jp = 0; jp < 2; jp++) {
                        float v0 = va[h][jp * 2], v1 = va[h][jp * 2 + 1];
                        half h0 = __float2half_rn(v0), h1 = __float2half_rn(v1);
                        half l0 = __float2half_rn(v0 - __half2float(h0));
                        half l1 = __float2half_rn(v1 - __half2float(h1));
                        Ahi[aidx[h][jp]] = __halves2half2(h0, h1);
                        Alo[aidx[h][jp]] = __halves2half2(l0, l1);
                        float w0 = vb[h][jp * 2], w1 = vb[h][jp * 2 + 1];
                        half g0 = __float2half_rn(w0), g1 = __float2half_rn(w1);
                        half m0 = __float2half_rn(w0 - __half2float(g0));
                        half m1 = __float2half_rn(w1 - __half2float(g1));
                        Bhi[bidx[h][jp]] = __halves2half2(g0, g1);
                        Blo[bidx[h][jp]] = __halves2half2(m0, m1);
                    }
                }
            }
            __syncthreads();
            if (ks < DD / 16 - 1) {
                int k0 = (ks + 1) * 16;
                ra0 = *reinterpret_cast<const float4*>(Ar0 + k0);
                ra1 = *reinterpret_cast<const float4*>(Ar1 + k0);
                rb0 = *reinterpret_cast<const float4*>(Br0 + k0);
                rb1 = *reinterpret_cast<const float4*>(Br1 + k0);
            }
            // fragment loads: one LDS.128 each
            uint4 AH[4], AL[4], BH[2], BL[2];
#pragma unroll
            for (int mt = 0; mt < 4; mt++) {
                AH[mt] = *reinterpret_cast<uint4*>(Ahi + (wm * 4 + mt) * 128 + swl * 4);
                AL[mt] = *reinterpret_cast<uint4*>(Alo + (wm * 4 + mt) * 128 + swl * 4);
            }
#pragma unroll
            for (int q = 0; q < 2; q++) {
                BH[q] = *reinterpret_cast<uint4*>(Bhi + (wn * 2 + q) * 128 + swl * 4);
                BL[q] = *reinterpret_cast<uint4*>(Blo + (wn * 2 + q) * 128 + swl * 4);
            }
#pragma unroll
            for (int nt = 0; nt < 4; nt++) {
                int q = nt >> 1, sub = nt & 1;
                uint32_t bh0 = sub ? BH[q].z : BH[q].x;
                uint32_t bh1 = sub ? BH[q].w : BH[q].y;
                uint32_t bl0 = sub ? BL[q].z : BL[q].x;
                uint32_t bl1 = sub ? BL[q].w : BL[q].y;
#pragma unroll
                for (int mt = 0; mt < 4; mt++) {
                    mma_f16(acc[mt][nt], AH[mt].x, AH[mt].y, AH[mt].z, AH[mt].w, bh0, bh1);
                    mma_f16(acc[mt][nt], AH[mt].x, AH[mt].y, AH[mt].z, AH[mt].w, bl0, bl1);
                    mma_f16(acc[mt][nt], AL[mt].x, AL[mt].y, AL[mt].z, AL[mt].w, bh0, bh1);
                }
            }
        }
        // fold c2, running argmin (v ascending within thread)
#pragma unroll
        for (int nt = 0; nt < 4; nt++) {
            int vbase = nch * 128 + wn * 32 + nt * 8 + tig * 2;
            float c0 = c2s[vbase], c1 = c2s[vbase + 1];
#pragma unroll
            for (int mt = 0; mt < 4; mt++) {
                float s0 = fmaf(-2.f, acc[mt][nt][0], c0);
                float s1 = fmaf(-2.f, acc[mt][nt][1], c1);
                float s2 = fmaf(-2.f, acc[mt][nt][2], c0);
                float s3 = fmaf(-2.f, acc[mt][nt][3], c1);
                int sl0 = mt * 2, sl1 = mt * 2 + 1;
                if (s0 < bestv[sl0]) { bestv[sl0] = s0; besti[sl0] = vbase; }
                if (s1 < bestv[sl0]) { bestv[sl0] = s1; besti[sl0] = vbase + 1; }
                if (s2 < bestv[sl1]) { bestv[sl1] = s2; besti[sl1] = vbase; }
                if (s3 < bestv[sl1]) { bestv[sl1] = s3; besti[sl1] = vbase + 1; }
            }
        }
    }

    // cross-thread reduce: 16 candidates per row
    __syncthreads();
#pragma unroll
    for (int mt = 0; mt < 4; mt++) {
#pragma unroll
        for (int h = 0; h < 2; h++) {
            int r = wm * 64 + mt * 16 + grp + h * 8;
            Sv[r * 16 + wn * 4 + tig] = bestv[mt * 2 + h];
            Si[r * 16 + wn * 4 + tig] = besti[mt * 2 + h];
        }
    }
    __syncthreads();
    if (tid < 128) {
        float bv = Sv[tid * 16];
        int   bi = Si[tid * 16];
#pragma unroll
        for (int u = 1; u < 16; u++) {
            float v2 = Sv[tid * 16 + u];
            int   i2 = Si[tid * 16 + u];
            if (v2 < bv || (v2 == bv && i2 < bi)) { bv = v2; bi = i2; }
        }
        ridx[tid] = bi;
        int b = btile * 128 + tid;
        out[(size_t)BB * TT * DD + (size_t)b * TT + t] = (float)bi;
    }
    __syncthreads();

    // gather epilogue
    const float4* cb4  = reinterpret_cast<const float4*>(cb);
    float4*       out4 = reinterpret_cast<float4*>(out);
    int rsub = tid >> 6, d4 = tid & 63;
#pragma unroll 4
    for (int r0 = 0; r0 < 128; r0 += 4) {
        int r   = r0 + rsub;
        int b   = btile * 128 + r;
        int idx = ridx[r];
        out4[((size_t)b * TT + t) * (DD / 4) + d4] =
            cb4[((size_t)t * VV + idx) * (DD / 4) + d4];
    }
}

// ---------------------------------------------------------------------------
#define DYN_SMEM (4096 * 4 + (VV + 128 * 16 * 2 + 128) * 4)

extern "C" void kernel_launch(void* const* d_in, const int* in_sizes, int n_in,
                              void* d_out, int out_size) {
    const float* x  = (const float*)d_in[0];   // (B, T, D) f32
    const float* cb = (const float*)d_in[1];   // (T, V, D) f32
    float* out = (float*)d_out;

    cudaFuncSetAttribute(vsq_mma_kernel, cudaFuncAttributeMaxDynamicSharedMemorySize, DYN_SMEM);
    c2_kernel<<<(TT * VV) / 8, 256>>>(cb);
    vsq_mma_kernel<<<dim3(BB / 128, TT), 256, DYN_SMEM>>>(x, cb, out);
}